// round 2
// baseline (speedup 1.0000x reference)
#include <cuda_runtime.h>
#include <math.h>

// Problem constants (fixed by the dataset)
#define BB 256
#define NN 2048
#define RR 64
#define DD 64
#define KK 2
#define TT 8
#define HH 128   // hidden = 2*D
#define KD 128   // K*D

// One CTA per graph (batch element). The embedding buffer IS d_out
// (float [B, N, D]). Sequential over nodes R..N-1; __syncthreads() orders
// each node's global write before the next node's parent gathers (block-scope
// visibility of global writes across __syncthreads is guaranteed).
__global__ __launch_bounds__(128, 2)
void dag_seq_kernel(const float* __restrict__ roots,
                    const float* __restrict__ W1,
                    const float* __restrict__ b1,
                    const float* __restrict__ W2,
                    const float* __restrict__ b2,
                    const int*   __restrict__ idx,
                    const int*   __restrict__ types,
                    float*       __restrict__ buf)
{
    const int b   = blockIdx.x;
    const int tid = threadIdx.x;

    __shared__ float xs[KD];     // gathered parent embeddings (x)
    __shared__ float hs[HH];     // hidden after GELU
    __shared__ float part[HH];   // partial sums for second matvec

    // ---- init: copy roots into buf[b, 0:R, :] (rest written by the loop) ----
    const float* rsrc  = roots + (size_t)b * (RR * DD);
    float*       bbase = buf   + (size_t)b * (NN * DD);
    #pragma unroll
    for (int i = tid; i < RR * DD; i += 128) bbase[i] = rsrc[i];
    __syncthreads();

    const int* idx_b = idx   + (size_t)b * (NN * KK);
    const int* typ_b = types + (size_t)b * NN;

    for (int pos = RR; pos < NN; ++pos) {
        // scalar per-step metadata (broadcast loads, same address per warp)
        const int typ = typ_b[pos];
        const int i0  = idx_b[pos * 2 + 0];
        const int i1  = idx_b[pos * 2 + 1];

        // ---- gather parents: x = concat(buf[b,i0,:], buf[b,i1,:]) ----
        if (tid < 64) xs[tid] = bbase[i0 * DD + tid];
        else          xs[tid] = bbase[i1 * DD + (tid - 64)];
        __syncthreads();

        // ---- h = gelu(x @ W1[typ] + b1[typ]) ; thread j computes h[j] ----
        // W1[t][i][j] at t*KD*H + i*H + j : consecutive j across threads => coalesced
        const float* w1 = W1 + (size_t)typ * (KD * HH);
        float a0 = 0.f, a1 = 0.f, a2 = 0.f, a3 = 0.f;
        #pragma unroll
        for (int i = 0; i < KD; i += 4) {
            a0 += xs[i + 0] * w1[(i + 0) * HH + tid];
            a1 += xs[i + 1] * w1[(i + 1) * HH + tid];
            a2 += xs[i + 2] * w1[(i + 2) * HH + tid];
            a3 += xs[i + 3] * w1[(i + 3) * HH + tid];
        }
        float acc = ((a0 + a1) + (a2 + a3)) + b1[typ * HH + tid];
        // exact GELU: 0.5*x*(1+erf(x/sqrt(2)))  (matches approximate=False)
        hs[tid] = 0.5f * acc * (1.0f + erff(acc * 0.70710678118654752440f));
        __syncthreads();

        // ---- out = h @ W2[typ] + b2[typ] ; split-K over 2 half-warps ----
        // W2[t][j][d] at t*H*D + j*D + d : consecutive d across threads => coalesced
        const float* w2   = W2 + (size_t)typ * (HH * DD);
        const int    d    = tid & 63;
        const int    half = tid >> 6;
        const float* hh   = hs + half * 64;
        const float* ww   = w2 + half * 64 * DD + d;
        float c0 = 0.f, c1 = 0.f;
        #pragma unroll
        for (int j = 0; j < 64; j += 2) {
            c0 += hh[j + 0] * ww[(j + 0) * DD];
            c1 += hh[j + 1] * ww[(j + 1) * DD];
        }
        part[tid] = c0 + c1;
        __syncthreads();

        if (tid < 64) {
            float o = part[tid] + part[tid + 64] + b2[typ * DD + tid];
            bbase[pos * DD + tid] = o;
        }
        __syncthreads();  // write visible + SMEM reusable before next step
    }
}

extern "C" void kernel_launch(void* const* d_in, const int* in_sizes, int n_in,
                              void* d_out, int out_size)
{
    // metadata order: root_embeddings, W1, b1, W2, b2, node_inputs_indices, node_types
    const float* roots = (const float*)d_in[0];
    const float* W1    = (const float*)d_in[1];
    const float* b1    = (const float*)d_in[2];
    const float* W2    = (const float*)d_in[3];
    const float* b2    = (const float*)d_in[4];
    const int*   idx   = (const int*)  d_in[5];
    const int*   typ   = (const int*)  d_in[6];
    float*       out   = (float*)d_out;

    dag_seq_kernel<<<BB, 128>>>(roots, W1, b1, W2, b2, idx, typ, out);
}

// round 4
// speedup vs baseline: 1.2588x; 1.2588x over previous
#include <cuda_runtime.h>
#include <math.h>

#define BB 256
#define NN 2048
#define RR 64
#define DD 64
#define TT 8
#define HH 128
#define KD 128

// One CTA per graph, 256 threads. Level-order schedule with per-(level,type)
// batching: up to 8 nodes share one streaming pass over W1/W2 (weight values
// register-cached, 8 FMAs per weight load).
__global__ __launch_bounds__(256, 2)
void dag_level_kernel(const float* __restrict__ roots,
                      const float* __restrict__ W1,
                      const float* __restrict__ b1,
                      const float* __restrict__ W2,
                      const float* __restrict__ b2,
                      const int*   __restrict__ g_idx,
                      const int*   __restrict__ g_typ,
                      float*       __restrict__ buf)
{
    const int b    = blockIdx.x;
    const int tid  = threadIdx.x;
    const int lane = tid & 31;
    const int wid  = tid >> 5;

    __shared__ unsigned short s_idx16[NN * 2];     // 8 KB  parent indices
    __shared__ unsigned char  s_type[NN];          // 2 KB
    __shared__ unsigned short s_order[NN];         // 4 KB  nodes sorted by level
    __shared__ unsigned short s_lstart[NN + 2];    // 4 KB  level offsets
    __shared__ union U1 { unsigned short lvl[NN];  // pre-loop
                          unsigned short gl[NN];   // main loop: group node list
                        } u1;                      // 4 KB
    __shared__ __align__(16)
               union U2 { unsigned int hist[NN];   // pre-loop histogram/cursor
                          float xs[128 * 12];      // main loop: X^T (pad 12)
                        } u2;                      // 8 KB
    __shared__ __align__(16) float s_hs[128 * 12]; // 6 KB  H^T (pad 12)
    __shared__ float s_red[2048];                  // 8 KB  reduction scratch
    __shared__ int   s_maxl;
    __shared__ int   s_cnt;

    const int* idx_b = g_idx + (size_t)b * (NN * 2);
    const int* typ_b = g_typ + (size_t)b * NN;
    float*     bbase = buf   + (size_t)b * (NN * DD);

    // ---------- phase A: stage metadata, zero hist, copy roots ----------
    for (int k = tid; k < NN * 2; k += 256) s_idx16[k] = (unsigned short)idx_b[k];
    for (int n = tid; n < NN; n += 256) {
        s_type[n] = (unsigned char)typ_b[n];
        u2.hist[n] = 0u;
        if (n < RR) u1.lvl[n] = 0;
    }
    {
        const float* rsrc = roots + (size_t)b * (RR * DD);
        for (int i = tid; i < RR * DD; i += 256) bbase[i] = rsrc[i];
    }
    __syncthreads();

    // ---------- phase B: exact level computation (serial, parents < n) ----------
    if (tid == 0) {
        int maxl = 0;
        for (int n = RR; n < NN; ++n) {
            int l0 = u1.lvl[s_idx16[n * 2 + 0]];
            int l1 = u1.lvl[s_idx16[n * 2 + 1]];
            int l  = 1 + (l0 > l1 ? l0 : l1);
            u1.lvl[n] = (unsigned short)l;
            if (l > maxl) maxl = l;
        }
        s_maxl = maxl;
    }
    __syncthreads();

    // ---------- phase C: counting sort by level ----------
    for (int n = RR + tid; n < NN; n += 256)
        atomicAdd(&u2.hist[u1.lvl[n]], 1u);
    __syncthreads();
    if (tid == 0) {
        const int maxl = s_maxl;
        unsigned int off = 0;
        for (int l = 1; l <= maxl; ++l) {
            s_lstart[l] = (unsigned short)off;
            unsigned int c = u2.hist[l];
            u2.hist[l] = off;          // becomes scatter cursor
            off += c;
        }
        s_lstart[maxl + 1] = (unsigned short)off;   // == NN-RR
    }
    __syncthreads();
    for (int n = RR + tid; n < NN; n += 256) {
        unsigned int pos = atomicAdd(&u2.hist[u1.lvl[n]], 1u);
        s_order[pos] = (unsigned short)n;
    }
    __syncthreads();   // hist & lvl dead; xs/gl regions free

    // ---------- main loop: levels x types ----------
    const int maxl = s_maxl;
    const int j128 = tid & 127;          // GEMM1 output column
    const int s2   = tid >> 7;           // GEMM1 i-half (0/1)
    const int d64  = tid & 63;           // GEMM2 output column
    const int s4   = tid >> 6;           // GEMM2 j-quarter (0..3)

    for (int L = 1; L <= maxl; ++L) {
        const int lo = s_lstart[L];
        const int hi = s_lstart[L + 1];

        for (int t = 0; t < TT; ++t) {
            // -- warp 0: ordered compaction of type-t nodes at this level --
            if (wid == 0) {
                int cnt = 0;
                for (int base = lo; base < hi; base += 32) {
                    int p = base + lane;
                    int nn = (p < hi) ? (int)s_order[p] : 0;
                    bool match = (p < hi) && (s_type[nn] == (unsigned char)t);
                    unsigned int mask = __ballot_sync(0xffffffffu, match);
                    if (match) {
                        int pos = cnt + __popc(mask & ((1u << lane) - 1u));
                        u1.gl[pos] = (unsigned short)nn;
                    }
                    cnt += __popc(mask);
                }
                if (lane == 0) s_cnt = cnt;
            }
            __syncthreads();
            const int cnt = s_cnt;
            if (cnt == 0) {
                // order the s_cnt read above before warp 0's write for the
                // next type (otherwise: data race on s_cnt)
                __syncthreads();
                continue;
            }

            const float* w1t = W1 + (size_t)t * (KD * HH);
            const float* w2t = W2 + (size_t)t * (HH * DD);

            for (int cb = 0; cb < cnt; cb += 8) {
                const int Mc = min(8, cnt - cb);

                // ---- gather: warp m loads node m's 128 inputs into xs^T ----
                if (wid < Mc) {
                    int node = u1.gl[cb + wid];
                    int p0 = s_idx16[node * 2 + 0];
                    int p1 = s_idx16[node * 2 + 1];
                    const float* r0 = bbase + p0 * DD;
                    const float* r1 = bbase + p1 * DD;
                    u2.xs[(lane      ) * 12 + wid] = r0[lane];
                    u2.xs[(lane + 32 ) * 12 + wid] = r0[lane + 32];
                    u2.xs[(lane + 64 ) * 12 + wid] = r1[lane];
                    u2.xs[(lane + 96 ) * 12 + wid] = r1[lane + 32];
                }
                __syncthreads();

                // ---- GEMM1: h[j][m] partial over i-half s2 ----
                {
                    float a0=0.f,a1=0.f,a2=0.f,a3=0.f,a4=0.f,a5=0.f,a6=0.f,a7=0.f;
                    const float* wp = w1t + (s2 * 64) * HH + j128;
                    const float* xp = u2.xs + (s2 * 64) * 12;
                    #pragma unroll 4
                    for (int i = 0; i < 64; ++i) {
                        float wv = __ldg(wp + i * HH);
                        float4 x0 = *(const float4*)(xp + i * 12);
                        float4 x1 = *(const float4*)(xp + i * 12 + 4);
                        a0 += x0.x * wv;  a1 += x0.y * wv;
                        a2 += x0.z * wv;  a3 += x0.w * wv;
                        a4 += x1.x * wv;  a5 += x1.y * wv;
                        a6 += x1.z * wv;  a7 += x1.w * wv;
                    }
                    float* rp = s_red + (s2 * 128 + j128) * 8;
                    rp[0]=a0; rp[1]=a1; rp[2]=a2; rp[3]=a3;
                    rp[4]=a4; rp[5]=a5; rp[6]=a6; rp[7]=a7;
                }
                __syncthreads();

                // ---- bias + GELU -> hs^T (threads 0..127) ----
                if (tid < 128) {
                    float bv = __ldg(b1 + t * HH + tid);
                    const float* r0 = s_red + tid * 8;
                    const float* r1 = s_red + 1024 + tid * 8;
                    #pragma unroll
                    for (int m = 0; m < 8; ++m) {
                        float h = r0[m] + r1[m] + bv;
                        s_hs[tid * 12 + m] =
                            0.5f * h * (1.0f + erff(h * 0.70710678118654752440f));
                    }
                }
                __syncthreads();

                // ---- GEMM2: out[d][m] partial over j-quarter s4 ----
                {
                    float a0=0.f,a1=0.f,a2=0.f,a3=0.f,a4=0.f,a5=0.f,a6=0.f,a7=0.f;
                    const float* wp = w2t + (s4 * 32) * DD + d64;
                    const float* hp = s_hs + (s4 * 32) * 12;
                    #pragma unroll 4
                    for (int j = 0; j < 32; ++j) {
                        float wv = __ldg(wp + j * DD);
                        float4 h0 = *(const float4*)(hp + j * 12);
                        float4 h1 = *(const float4*)(hp + j * 12 + 4);
                        a0 += h0.x * wv;  a1 += h0.y * wv;
                        a2 += h0.z * wv;  a3 += h0.w * wv;
                        a4 += h1.x * wv;  a5 += h1.y * wv;
                        a6 += h1.z * wv;  a7 += h1.w * wv;
                    }
                    float* rp = s_red + (s4 * 64 + d64) * 8;
                    rp[0]=a0; rp[1]=a1; rp[2]=a2; rp[3]=a3;
                    rp[4]=a4; rp[5]=a5; rp[6]=a6; rp[7]=a7;
                }
                __syncthreads();

                // ---- reduce 4 partials, add bias, write out (coalesced) ----
                {
                    // item = m*64 + d ; threads handle items tid and tid+256
                    #pragma unroll
                    for (int r = 0; r < 2; ++r) {
                        int item = tid + r * 256;
                        int m = item >> 6;
                        int d = item & 63;
                        if (m < Mc) {
                            float v = s_red[(0 * 64 + d) * 8 + m]
                                    + s_red[(1 * 64 + d) * 8 + m]
                                    + s_red[(2 * 64 + d) * 8 + m]
                                    + s_red[(3 * 64 + d) * 8 + m]
                                    + __ldg(b2 + t * DD + d);
                            int node = u1.gl[cb + m];
                            bbase[node * DD + d] = v;
                        }
                    }
                }
                __syncthreads();   // outputs visible before next gather
            }
        }
    }
}

extern "C" void kernel_launch(void* const* d_in, const int* in_sizes, int n_in,
                              void* d_out, int out_size)
{
    const float* roots = (const float*)d_in[0];
    const float* W1    = (const float*)d_in[1];
    const float* b1    = (const float*)d_in[2];
    const float* W2    = (const float*)d_in[3];
    const float* b2    = (const float*)d_in[4];
    const int*   idx   = (const int*)  d_in[5];
    const int*   typ   = (const int*)  d_in[6];
    float*       out   = (float*)d_out;

    dag_level_kernel<<<BB, 256>>>(roots, W1, b1, W2, b2, idx, typ, out);
}